// round 15
// baseline (speedup 1.0000x reference)
#include <cuda_runtime.h>
#include <cuda_bf16.h>
#include <cstdint>

#define NLAYERS 4
#define KCODES  1024
#define FDIM    512
#define BM      128
#define BN      64
#define KT      32
#define NSTK    (FDIM / KT)      // 16 k-tiles
#define NCHUNK  (KCODES / BN)    // 16 n-chunks
#define NSTEPS  (NCHUNK * NSTK)  // 256
#define MAXR    100352
#define NTHREADS 256

// ---------------- global scratch ----------------
__device__ __align__(16) float          g_R  [(size_t)MAXR * FDIM];
__device__ __align__(16) __nv_bfloat16  g_Rhi[(size_t)MAXR * FDIM];
__device__ __align__(16) __nv_bfloat16  g_Rmd[(size_t)MAXR * FDIM];
__device__ float g_x2[MAXR];
__device__ __align__(16) __nv_bfloat16  g_Chi[NLAYERS * KCODES * FDIM];
__device__ __align__(16) __nv_bfloat16  g_Cmd[NLAYERS * KCODES * FDIM];
__device__ float g_c2[NLAYERS * KCODES];

// ---------------- helpers ----------------
__device__ __forceinline__ uint32_t smem_u32(const void* p) {
    uint32_t a;
    asm("{ .reg .u64 t; cvta.to.shared.u64 t, %1; cvt.u32.u64 %0, t; }" : "=r"(a) : "l"(p));
    return a;
}
// SW64 swizzle for 64B rows: XOR row bits [7:8] into 16B-chunk bits [4:5]
#define SWZ64(o) ((o) ^ (((o) >> 3) & 0x30))

__device__ __forceinline__ void cp_async16(uint32_t saddr, const void* gaddr) {
    asm volatile("cp.async.cg.shared.global [%0], [%1], 16;"
                 :: "r"(saddr), "l"(gaddr) : "memory");
}
#define CP_COMMIT() asm volatile("cp.async.commit_group;" ::: "memory")
#define CP_WAIT2()  asm volatile("cp.async.wait_group 2;" ::: "memory")

__device__ __forceinline__ void ldm_x4(uint32_t* r, uint32_t addr) {
    asm volatile("ldmatrix.sync.aligned.m8n8.x4.shared.b16 {%0,%1,%2,%3}, [%4];"
                 : "=r"(r[0]), "=r"(r[1]), "=r"(r[2]), "=r"(r[3]) : "r"(addr));
}
__device__ __forceinline__ void mma16816(float* c, const uint32_t* a,
                                         uint32_t b0, uint32_t b1) {
    asm volatile("mma.sync.aligned.m16n8k16.row.col.f32.bf16.bf16.f32 "
                 "{%0,%1,%2,%3}, {%4,%5,%6,%7}, {%8,%9}, {%0,%1,%2,%3};"
                 : "+f"(c[0]), "+f"(c[1]), "+f"(c[2]), "+f"(c[3])
                 : "r"(a[0]), "r"(a[1]), "r"(a[2]), "r"(a[3]), "r"(b0), "r"(b1));
}

__device__ __forceinline__ unsigned fmono(float f) {
    unsigned u = __float_as_uint(f);
    return (u & 0x80000000u) ? ~u : (u | 0x80000000u);
}
__device__ __forceinline__ void split2(float x, __nv_bfloat16& h, __nv_bfloat16& m) {
    h = __float2bfloat16(x);
    float r1 = x - __bfloat162float(h);
    m = __float2bfloat16(r1);
}

// ---------------- prep kernels ----------------
__global__ void cbprep_kernel(const float* __restrict__ cb) {
    size_t i0 = ((size_t)blockIdx.x * 256 + threadIdx.x) * 4;
    if (i0 >= (size_t)NLAYERS * KCODES * FDIM) return;
    #pragma unroll
    for (int j = 0; j < 4; ++j) {
        size_t i = i0 + j;
        __nv_bfloat16 h, m;
        split2(cb[i], h, m);
        g_Chi[i] = h; g_Cmd[i] = m;
    }
}

__global__ void c2_kernel(const float* __restrict__ cb) {
    int code = blockIdx.x * 8 + (threadIdx.x >> 5);
    int lane = threadIdx.x & 31;
    if (code >= NLAYERS * KCODES) return;
    const float* row = cb + (size_t)code * FDIM;
    double s = 0.0;
    for (int k = lane; k < FDIM; k += 32) { double v = (double)row[k]; s += v * v; }
    #pragma unroll
    for (int off = 16; off; off >>= 1) s += __shfl_xor_sync(0xffffffffu, s, off);
    if (lane == 0) g_c2[code] = (float)s;
}

__global__ void init_kernel(const float* __restrict__ data, int nrows) {
    int r = blockIdx.x * 8 + (threadIdx.x >> 5);
    int lane = threadIdx.x & 31;
    if (r >= nrows) return;
    const float4* src = (const float4*)(data + (size_t)r * FDIM);
    float4* Rr = (float4*)(g_R + (size_t)r * FDIM);
    double ss = 0.0;
    #pragma unroll
    for (int j = 0; j < 4; ++j) {
        int q = lane + 32 * j;
        float4 v = src[q];
        Rr[q] = v;
        float vv[4] = {v.x, v.y, v.z, v.w};
        __nv_bfloat16 h[4], m[4];
        #pragma unroll
        for (int c = 0; c < 4; ++c) {
            split2(vv[c], h[c], m[c]);
            ss += (double)vv[c] * vv[c];
        }
        size_t e = (size_t)r * FDIM + (size_t)q * 4;
        __nv_bfloat162 t;
        t.x=h[0]; t.y=h[1]; *(__nv_bfloat162*)(g_Rhi+e)   = t;
        t.x=h[2]; t.y=h[3]; *(__nv_bfloat162*)(g_Rhi+e+2) = t;
        t.x=m[0]; t.y=m[1]; *(__nv_bfloat162*)(g_Rmd+e)   = t;
        t.x=m[2]; t.y=m[3]; *(__nv_bfloat162*)(g_Rmd+e+2) = t;
    }
    #pragma unroll
    for (int off = 16; off; off >>= 1) ss += __shfl_xor_sync(0xffffffffu, ss, off);
    if (lane == 0) g_x2[r] = (float)ss;
}

// ---------------- layer kernel ----------------
// smem map (bytes):
//   [0,512)       x2s float[128]
//   [512,4608)    c2s float[1024]
//   [4608,8704)   top u64[128][2][2]
//   [8704,9216)   bidx u32[128]
//   [9216,...)    4 stages x (Ahi 8K | Amd 8K | Bhi 4K | Bmd 4K) = 24K/stage
#define SM_X2    0
#define SM_C2    512
#define SM_TOP   4608
#define SM_BIDX  8704
#define SM_TILE  9216
#define STAGE_SZ 24576
#define SMEM_TOTAL (SM_TILE + 4 * STAGE_SZ)   // 107520 B -> 2 CTAs/SM

__global__ __launch_bounds__(NTHREADS, 2)
void layer_kernel(const float* __restrict__ cb, const float* __restrict__ data,
                  void* __restrict__ out_raw, int nrows, int layer, int mode) {
    extern __shared__ char smem[];
    const uint32_t sb = smem_u32(smem);
    const int tid = threadIdx.x, wid = tid >> 5, lane = tid & 31;
    const int wm = wid & 3, wn = wid >> 2;     // 4 warps M x 2 warps N (32x32 per warp)
    const int row0 = blockIdx.x * BM;

    float* x2s = (float*)(smem + SM_X2);
    float* c2s = (float*)(smem + SM_C2);
    unsigned long long* topsm = (unsigned long long*)(smem + SM_TOP);

    for (int i = tid; i < KCODES; i += NTHREADS) c2s[i] = g_c2[layer * KCODES + i];
    if (tid < BM) {
        int r = min(row0 + tid, nrows - 1);
        x2s[tid] = g_x2[r];
    }
    __syncthreads();

    // stage loader: A = 128 rows x 64B (SW64), B = 64 rows x 64B (SW64)
    auto load_stage = [&](int stg, int chunk, int ktile) {
        const int n0 = chunk * BN;
        const uint32_t sbase = sb + SM_TILE + stg * STAGE_SZ;
        #pragma unroll
        for (int t = 0; t < 2; ++t) {             // A splits
            const __nv_bfloat16* src = (t == 0) ? g_Rhi : g_Rmd;
            const uint32_t base = sbase + t * 8192;
            #pragma unroll
            for (int j = 0; j < 2; ++j) {
                int i = tid + NTHREADS * j;
                int row = i >> 2, c16 = i & 3;
                int rg = min(row0 + row, nrows - 1);
                cp_async16(base + SWZ64(row * 64 + c16 * 16),
                           src + (size_t)rg * FDIM + ktile * KT + c16 * 8);
            }
        }
        #pragma unroll
        for (int t = 0; t < 2; ++t) {             // B splits
            const __nv_bfloat16* src = (t == 0) ? g_Chi : g_Cmd;
            const uint32_t base = sbase + 16384 + t * 4096;
            int row = tid >> 2, c16 = tid & 3;
            int rg = layer * KCODES + n0 + row;
            cp_async16(base + SWZ64(row * 64 + c16 * 16),
                       src + (size_t)rg * FDIM + ktile * KT + c16 * 8);
        }
    };

    float acc[2][4][4];
    #pragma unroll
    for (int mf = 0; mf < 2; ++mf)
        #pragma unroll
        for (int nf = 0; nf < 4; ++nf)
            #pragma unroll
            for (int q = 0; q < 4; ++q) acc[mf][nf][q] = 0.f;

    unsigned long long tk1[4], tk2[4];
    #pragma unroll
    for (int s = 0; s < 4; ++s) { tk1[s] = ~0ull; tk2[s] = ~0ull; }

    // prologue: fill stages 0..2
    #pragma unroll
    for (int p = 0; p < 3; ++p) {
        load_stage(p, p >> 4, p & 15);
        CP_COMMIT();
    }

    for (int step = 0; step < NSTEPS; ++step) {
        const int chunk = step >> 4, ktile = step & 15, stg = step & 3;
        CP_WAIT2();            // stage stg complete (3 groups always pending)
        __syncthreads();       // publish loads; also: all warps done reading stage (step-1)&3

        // prefetch step+3 into stage (step+3)&3 (== (step-1)&3, safe after sync)
        if (step + 3 < NSTEPS) {
            load_stage((step + 3) & 3, (step + 3) >> 4, (step + 3) & 15);
        }
        CP_COMMIT();           // always commit (possibly empty) to keep pending count at 3

        const uint32_t sbase = sb + SM_TILE + stg * STAGE_SZ;
        const uint32_t ahiB = sbase, amdB = sbase + 8192;
        const uint32_t bhiB = sbase + 16384, bmdB = sbase + 20480;

        #pragma unroll
        for (int ks = 0; ks < 2; ++ks) {
            uint32_t ah[2][4], am[2][4], bh[2][4], bm[2][4];
            #pragma unroll
            for (int mf = 0; mf < 2; ++mf) {
                int arow = wm * 32 + mf * 16 + (lane & 15);
                int akc  = ks * 2 + (lane >> 4);
                uint32_t aoff = SWZ64(arow * 64 + akc * 16);
                ldm_x4(ah[mf], ahiB + aoff);
                ldm_x4(am[mf], amdB + aoff);
            }
            #pragma unroll
            for (int nf2 = 0; nf2 < 2; ++nf2) {
                int g = lane >> 3;
                int brow = wn * 32 + nf2 * 16 + ((g >> 1) << 3) + (lane & 7);
                int bkc  = ks * 2 + (g & 1);
                uint32_t boff = SWZ64(brow * 64 + bkc * 16);
                ldm_x4(bh[nf2], bhiB + boff);
                ldm_x4(bm[nf2], bmdB + boff);
            }
            #pragma unroll
            for (int mf = 0; mf < 2; ++mf)
                #pragma unroll
                for (int nf2 = 0; nf2 < 2; ++nf2) {
                    float* a0 = acc[mf][nf2 * 2 + 0];
                    float* a1 = acc[mf][nf2 * 2 + 1];
                    mma16816(a0, ah[mf], bh[nf2][0], bh[nf2][1]);   // hh
                    mma16816(a1, ah[mf], bh[nf2][2], bh[nf2][3]);
                    mma16816(a0, ah[mf], bm[nf2][0], bm[nf2][1]);   // hm
                    mma16816(a1, ah[mf], bm[nf2][2], bm[nf2][3]);
                    mma16816(a0, am[mf], bh[nf2][0], bh[nf2][1]);   // mh
                    mma16816(a1, am[mf], bh[nf2][2], bh[nf2][3]);
                }
        }

        // ---- per-chunk epilogue: approx score, fold per-lane top-2 ----
        if (ktile == 15) {
            const int n0 = chunk * BN;
            #pragma unroll
            for (int mf = 0; mf < 2; ++mf) {
                int rA = wm * 32 + mf * 16 + (lane >> 2);
                int rB = rA + 8;
                float x2A = x2s[rA], x2B = x2s[rB];
                #pragma unroll
                for (int nf = 0; nf < 4; ++nf) {
                    int col = wn * 32 + nf * 8 + (lane & 3) * 2;
                    #pragma unroll
                    for (int e = 0; e < 2; ++e) {
                        int idxc = n0 + col + e;
                        float cc = c2s[idxc];
                        float scA = __fsub_rn(__fadd_rn(x2A, cc),
                                              __fmul_rn(2.0f, acc[mf][nf][e]));
                        float scB = __fsub_rn(__fadd_rn(x2B, cc),
                                              __fmul_rn(2.0f, acc[mf][nf][2 + e]));
                        unsigned long long keyA =
                            ((unsigned long long)fmono(scA) << 32) | (unsigned)idxc;
                        unsigned long long keyB =
                            ((unsigned long long)fmono(scB) << 32) | (unsigned)idxc;
                        int sA = mf * 2, sB = mf * 2 + 1;
                        if (keyA < tk1[sA]) { tk2[sA] = tk1[sA]; tk1[sA] = keyA; }
                        else if (keyA < tk2[sA]) tk2[sA] = keyA;
                        if (keyB < tk1[sB]) { tk2[sB] = tk1[sB]; tk1[sB] = keyB; }
                        else if (keyB < tk2[sB]) tk2[sB] = keyB;
                    }
                }
                #pragma unroll
                for (int nf = 0; nf < 4; ++nf)
                    #pragma unroll
                    for (int q = 0; q < 4; ++q) acc[mf][nf][q] = 0.f;
            }
        }
    }
    __syncthreads();

    // ---- quad merge of per-lane top-2 -> smem per (row, wn) ----
    #pragma unroll
    for (int s = 0; s < 4; ++s) {
        unsigned long long a = tk1[s], b = tk2[s];
        #pragma unroll
        for (int off = 1; off <= 2; off <<= 1) {
            unsigned long long oa = __shfl_xor_sync(0xffffffffu, a, off);
            unsigned long long ob = __shfl_xor_sync(0xffffffffu, b, off);
            unsigned long long n1 = (a < oa) ? a : oa;
            unsigned long long hi = (a < oa) ? oa : a;
            unsigned long long lo2 = (b < ob) ? b : ob;
            b = (hi < lo2) ? hi : lo2;
            a = n1;
        }
        if ((lane & 3) == 0) {
            int row = wm * 32 + (s >> 1) * 16 + (lane >> 2) + (s & 1) * 8;
            topsm[row * 4 + wn * 2 + 0] = a;
            topsm[row * 4 + wn * 2 + 1] = b;
        }
    }
    __syncthreads();

    // ---- fp64 exact rescore of top-2 candidates (warp per row) ----
    const float* cbl = cb + (size_t)layer * KCODES * FDIM;
    for (int m = wid; m < BM; m += 8) {
        if (row0 + m >= nrows) continue;
        unsigned long long k1 = ~0ull, k2 = ~0ull;
        #pragma unroll
        for (int i = 0; i < 4; ++i) {
            unsigned long long v = topsm[m * 4 + i];
            if (v < k1) { k2 = k1; k1 = v; }
            else if (v < k2) k2 = v;
        }
        unsigned c1i = (unsigned)(k1 & 0xFFFFFFFFull);
        unsigned c2i = (unsigned)(k2 & 0xFFFFFFFFull);

        const float* Rr = g_R + (size_t)(row0 + m) * FDIM;
        const float* q1 = cbl + (size_t)c1i * FDIM;
        const float* q2 = cbl + (size_t)c2i * FDIM;
        double d1 = 0.0, d2 = 0.0;
        #pragma unroll
        for (int j = 0; j < 16; ++j) {
            int k = lane + 32 * j;
            double rv = (double)Rr[k];
            d1 += rv * (double)q1[k];
            d2 += rv * (double)q2[k];
        }
        #pragma unroll
        for (int off = 16; off; off >>= 1) {
            d1 += __shfl_xor_sync(0xffffffffu, d1, off);
            d2 += __shfl_xor_sync(0xffffffffu, d2, off);
        }
        if (lane == 0) {
            float x2 = x2s[m];
            float s1 = __fsub_rn(__fadd_rn(x2, c2s[c1i]), __fmul_rn(2.0f, (float)d1));
            float s2 = __fsub_rn(__fadd_rn(x2, c2s[c2i]), __fmul_rn(2.0f, (float)d2));
            unsigned pick;
            if (s1 < s2)      pick = c1i;
            else if (s2 < s1) pick = c2i;
            else              pick = (c1i < c2i) ? c1i : c2i;
            ((unsigned*)(smem + SM_BIDX))[m] = pick;
            size_t o = (size_t)(row0 + m) * NLAYERS + layer;
            if (mode == 0)      ((float*)out_raw)[o] = (float)pick;
            else if (mode == 2) ((long long*)out_raw)[o] = (long long)pick;
        }
    }
    __syncthreads();

    // ---- residual update: warp per row; next-layer splits + x2; recon on last ----
    float* recon = (mode == 1) ? (float*)out_raw
                               : ((float*)out_raw + (size_t)nrows * NLAYERS);
    for (int m = wid; m < BM; m += 8) {
        int row = row0 + m;
        if (row >= nrows) continue;
        unsigned idx = ((unsigned*)(smem + SM_BIDX))[m];
        const float4* cbr = (const float4*)(cb + ((size_t)layer * KCODES + idx) * FDIM);
        float4* Rr = (float4*)(g_R + (size_t)row * FDIM);
        double ss = 0.0;
        #pragma unroll
        for (int j = 0; j < 4; ++j) {
            int q = lane + 32 * j;
            float4 rv = Rr[q], cv = cbr[q];
            rv.x -= cv.x; rv.y -= cv.y; rv.z -= cv.z; rv.w -= cv.w;
            Rr[q] = rv;
            if (layer == NLAYERS - 1) {
                if (mode != 2) {
                    float4 dv = ((const float4*)(data + (size_t)row * FDIM))[q];
                    float4 rc = {dv.x - rv.x, dv.y - rv.y, dv.z - rv.z, dv.w - rv.w};
                    ((float4*)(recon + (size_t)row * FDIM))[q] = rc;
                }
            } else {
                float vv[4] = {rv.x, rv.y, rv.z, rv.w};
                __nv_bfloat16 h[4], md[4];
                #pragma unroll
                for (int c = 0; c < 4; ++c) {
                    split2(vv[c], h[c], md[c]);
                    ss += (double)vv[c] * vv[c];
                }
                size_t e = (size_t)row * FDIM + (size_t)q * 4;
                __nv_bfloat162 t;
                t.x=h[0];  t.y=h[1];  *(__nv_bfloat162*)(g_Rhi+e)   = t;
                t.x=h[2];  t.y=h[3];  *(__nv_bfloat162*)(g_Rhi+e+2) = t;
                t.x=md[0]; t.y=md[1]; *(__nv_bfloat162*)(g_Rmd+e)   = t;
                t.x=md[2]; t.y=md[3]; *(__nv_bfloat162*)(g_Rmd+e+2) = t;
            }
        }
        if (layer != NLAYERS - 1) {
            #pragma unroll
            for (int off = 16; off; off >>= 1) ss += __shfl_xor_sync(0xffffffffu, ss, off);
            if (lane == 0) g_x2[row] = (float)ss;
        }
    }
}

// ---------------- host ----------------
extern "C" void kernel_launch(void* const* d_in, const int* in_sizes, int n_in,
                              void* d_out, int out_size) {
    const float* data = (const float*)d_in[0];
    const float* cb   = (const float*)d_in[1];
    int nrows = in_sizes[0] / FDIM;

    long long n_both  = (long long)nrows * (NLAYERS + FDIM);
    long long n_recon = (long long)nrows * FDIM;
    long long n_codes = (long long)nrows * NLAYERS;
    int mode = 0;
    if ((long long)out_size == n_recon)      mode = 1;
    else if ((long long)out_size == n_codes) mode = 2;
    else if ((long long)out_size == n_both)  mode = 0;

    cudaFuncSetAttribute(layer_kernel, cudaFuncAttributeMaxDynamicSharedMemorySize,
                         SMEM_TOTAL);

    cbprep_kernel<<<(NLAYERS * KCODES * FDIM / 4 + 255) / 256, 256>>>(cb);
    c2_kernel<<<(NLAYERS * KCODES + 7) / 8, 256>>>(cb);
    init_kernel<<<(nrows + 7) / 8, 256>>>(data, nrows);

    int grid = (nrows + BM - 1) / BM;
    for (int l = 0; l < NLAYERS; ++l)
        layer_kernel<<<grid, NTHREADS, SMEM_TOTAL>>>(cb, data, d_out, nrows, l, mode);
}

// round 17
// speedup vs baseline: 1.1757x; 1.1757x over previous
#include <cuda_runtime.h>
#include <cuda_bf16.h>
#include <cstdint>

#define NLAYERS 4
#define KCODES  1024
#define FDIM    512
#define BM      128
#define BN      64
#define KT      64
#define NSTK    (FDIM / KT)      // 8 k-tiles
#define NCHUNK  (KCODES / BN)    // 16 n-chunks
#define NSTEPS  (NCHUNK * NSTK)  // 128
#define MAXR    100352
#define NTHREADS 256

// ---------------- global scratch ----------------
__device__ __align__(16) float          g_R  [(size_t)MAXR * FDIM];
__device__ __align__(16) __nv_bfloat16  g_Rhi[(size_t)MAXR * FDIM];
__device__ __align__(16) __nv_bfloat16  g_Rmd[(size_t)MAXR * FDIM];
__device__ float g_x2[MAXR];
__device__ __align__(16) __nv_bfloat16  g_Chi[NLAYERS * KCODES * FDIM];
__device__ __align__(16) __nv_bfloat16  g_Cmd[NLAYERS * KCODES * FDIM];
__device__ float g_c2[NLAYERS * KCODES];

// ---------------- helpers ----------------
__device__ __forceinline__ uint32_t smem_u32(const void* p) {
    uint32_t a;
    asm("{ .reg .u64 t; cvta.to.shared.u64 t, %1; cvt.u32.u64 %0, t; }" : "=r"(a) : "l"(p));
    return a;
}
#define SWZ128(o) ((o) ^ (((o) >> 3) & 0x70))

__device__ __forceinline__ void cp_async16(uint32_t saddr, const void* gaddr) {
    asm volatile("cp.async.cg.shared.global [%0], [%1], 16;"
                 :: "r"(saddr), "l"(gaddr) : "memory");
}
#define CP_COMMIT() asm volatile("cp.async.commit_group;" ::: "memory")
#define CP_WAIT0()  asm volatile("cp.async.wait_group 0;" ::: "memory")

__device__ __forceinline__ void ldm_x4(uint32_t* r, uint32_t addr) {
    asm volatile("ldmatrix.sync.aligned.m8n8.x4.shared.b16 {%0,%1,%2,%3}, [%4];"
                 : "=r"(r[0]), "=r"(r[1]), "=r"(r[2]), "=r"(r[3]) : "r"(addr));
}
__device__ __forceinline__ void mma16816(float* c, const uint32_t* a,
                                         uint32_t b0, uint32_t b1) {
    asm volatile("mma.sync.aligned.m16n8k16.row.col.f32.bf16.bf16.f32 "
                 "{%0,%1,%2,%3}, {%4,%5,%6,%7}, {%8,%9}, {%0,%1,%2,%3};"
                 : "+f"(c[0]), "+f"(c[1]), "+f"(c[2]), "+f"(c[3])
                 : "r"(a[0]), "r"(a[1]), "r"(a[2]), "r"(a[3]), "r"(b0), "r"(b1));
}

__device__ __forceinline__ unsigned fmono(float f) {
    unsigned u = __float_as_uint(f);
    return (u & 0x80000000u) ? ~u : (u | 0x80000000u);
}
__device__ __forceinline__ void split2(float x, __nv_bfloat16& h, __nv_bfloat16& m) {
    h = __float2bfloat16(x);
    float r1 = x - __bfloat162float(h);
    m = __float2bfloat16(r1);
}

// ---------------- prep kernels ----------------
__global__ void cbprep_kernel(const float* __restrict__ cb) {
    size_t i0 = ((size_t)blockIdx.x * 256 + threadIdx.x) * 4;
    if (i0 >= (size_t)NLAYERS * KCODES * FDIM) return;
    #pragma unroll
    for (int j = 0; j < 4; ++j) {
        size_t i = i0 + j;
        __nv_bfloat16 h, m;
        split2(cb[i], h, m);
        g_Chi[i] = h; g_Cmd[i] = m;
    }
}

__global__ void c2_kernel(const float* __restrict__ cb) {
    int code = blockIdx.x * 8 + (threadIdx.x >> 5);
    int lane = threadIdx.x & 31;
    if (code >= NLAYERS * KCODES) return;
    const float* row = cb + (size_t)code * FDIM;
    double s = 0.0;
    for (int k = lane; k < FDIM; k += 32) { double v = (double)row[k]; s += v * v; }
    #pragma unroll
    for (int off = 16; off; off >>= 1) s += __shfl_xor_sync(0xffffffffu, s, off);
    if (lane == 0) g_c2[code] = (float)s;
}

__global__ void init_kernel(const float* __restrict__ data, int nrows) {
    int r = blockIdx.x * 8 + (threadIdx.x >> 5);
    int lane = threadIdx.x & 31;
    if (r >= nrows) return;
    const float4* src = (const float4*)(data + (size_t)r * FDIM);
    float4* Rr = (float4*)(g_R + (size_t)r * FDIM);
    double ss = 0.0;
    #pragma unroll
    for (int j = 0; j < 4; ++j) {
        int q = lane + 32 * j;
        float4 v = src[q];
        Rr[q] = v;
        float vv[4] = {v.x, v.y, v.z, v.w};
        __nv_bfloat16 h[4], m[4];
        #pragma unroll
        for (int c = 0; c < 4; ++c) {
            split2(vv[c], h[c], m[c]);
            ss += (double)vv[c] * vv[c];
        }
        size_t e = (size_t)r * FDIM + (size_t)q * 4;
        __nv_bfloat162 t;
        t.x=h[0]; t.y=h[1]; *(__nv_bfloat162*)(g_Rhi+e)   = t;
        t.x=h[2]; t.y=h[3]; *(__nv_bfloat162*)(g_Rhi+e+2) = t;
        t.x=m[0]; t.y=m[1]; *(__nv_bfloat162*)(g_Rmd+e)   = t;
        t.x=m[2]; t.y=m[3]; *(__nv_bfloat162*)(g_Rmd+e+2) = t;
    }
    #pragma unroll
    for (int off = 16; off; off >>= 1) ss += __shfl_xor_sync(0xffffffffu, ss, off);
    if (lane == 0) g_x2[r] = (float)ss;
}

// ---------------- layer kernel ----------------
// smem map (bytes):
//   [0,512)       x2s float[128]
//   [512,4608)    c2s float[1024]
//   [4608,8704)   top u64[128][2][2]
//   [8704,9216)   bidx u32[128]
//   [9216,...)    tiles: 2 stages x (Ahi 16K | Amd 16K | Bhi 8K | Bmd 8K)
#define SM_X2    0
#define SM_C2    512
#define SM_TOP   4608
#define SM_BIDX  8704
#define SM_TILE  9216
#define STAGE_SZ 49152
#define SMEM_TOTAL (SM_TILE + 2 * STAGE_SZ)   // 107520 B -> 2 CTAs/SM

__global__ __launch_bounds__(NTHREADS, 2)
void layer_kernel(const float* __restrict__ cb, const float* __restrict__ data,
                  void* __restrict__ out_raw, int nrows, int layer, int mode) {
    extern __shared__ char smem[];
    const uint32_t sb = smem_u32(smem);
    const int tid = threadIdx.x, wid = tid >> 5, lane = tid & 31;
    const int wm = wid & 3, wn = wid >> 2;     // 4 warps M x 2 warps N (32x32 per warp)
    const int row0 = blockIdx.x * BM;

    float* x2s = (float*)(smem + SM_X2);
    float* c2s = (float*)(smem + SM_C2);
    unsigned long long* topsm = (unsigned long long*)(smem + SM_TOP);

    for (int i = tid; i < KCODES; i += NTHREADS) c2s[i] = g_c2[layer * KCODES + i];
    if (tid < BM) {
        int r = min(row0 + tid, nrows - 1);
        x2s[tid] = g_x2[r];
    }
    __syncthreads();

    auto load_stage = [&](int stg, int chunk, int ktile) {
        const int n0 = chunk * BN;
        const uint32_t sbase = sb + SM_TILE + stg * STAGE_SZ;
        // A tiles: 128 rows x 128B each
        #pragma unroll
        for (int t = 0; t < 2; ++t) {
            const __nv_bfloat16* src = (t == 0) ? g_Rhi : g_Rmd;
            const uint32_t base = sbase + t * 16384;
            #pragma unroll
            for (int j = 0; j < 4; ++j) {
                int i = tid + NTHREADS * j;
                int row = i >> 3, c16 = i & 7;
                int rg = min(row0 + row, nrows - 1);
                cp_async16(base + SWZ128(row * 128 + c16 * 16),
                           src + (size_t)rg * FDIM + ktile * KT + c16 * 8);
            }
        }
        // B tiles: 64 rows x 128B each
        #pragma unroll
        for (int t = 0; t < 2; ++t) {
            const __nv_bfloat16* src = (t == 0) ? g_Chi : g_Cmd;
            const uint32_t base = sbase + 32768 + t * 8192;
            #pragma unroll
            for (int j = 0; j < 2; ++j) {
                int i = tid + NTHREADS * j;
                int row = i >> 3, c16 = i & 7;
                int rg = layer * KCODES + n0 + row;
                cp_async16(base + SWZ128(row * 128 + c16 * 16),
                           src + (size_t)rg * FDIM + ktile * KT + c16 * 8);
            }
        }
    };

    float acc[2][4][4];
    #pragma unroll
    for (int mf = 0; mf < 2; ++mf)
        #pragma unroll
        for (int nf = 0; nf < 4; ++nf)
            #pragma unroll
            for (int q = 0; q < 4; ++q) acc[mf][nf][q] = 0.f;

    unsigned long long tk1[4], tk2[4];
    #pragma unroll
    for (int s = 0; s < 4; ++s) { tk1[s] = ~0ull; tk2[s] = ~0ull; }

    load_stage(0, 0, 0);
    CP_COMMIT();

    for (int step = 0; step < NSTEPS; ++step) {
        const int chunk = step >> 3, ktile = step & 7, stg = step & 1;

        CP_WAIT0();            // stage stg data arrived (only its group is pending)
        __syncthreads();       // publish stage stg; all warps done reading stage stg^1

        // Issue next stage AFTER the sync: writing stg^1 is now provably safe,
        // eliminating the bottom-of-loop barrier entirely.
        if (step + 1 < NSTEPS) {
            load_stage(stg ^ 1, (step + 1) >> 3, (step + 1) & 7);
            CP_COMMIT();
        }

        const uint32_t sbase = sb + SM_TILE + stg * STAGE_SZ;
        const uint32_t ahiB = sbase, amdB = sbase + 16384;
        const uint32_t bhiB = sbase + 32768, bmdB = sbase + 40960;

        #pragma unroll
        for (int ks = 0; ks < 4; ++ks) {
            // cached fragments: 8 LDSM feed 24 MMAs
            uint32_t ah[2][4], am[2][4], bh[2][4], bm[2][4];
            #pragma unroll
            for (int mf = 0; mf < 2; ++mf) {
                int arow = wm * 32 + mf * 16 + (lane & 15);
                int akc  = ks * 2 + (lane >> 4);
                uint32_t aoff = SWZ128(arow * 128 + akc * 16);
                ldm_x4(ah[mf], ahiB + aoff);
                ldm_x4(am[mf], amdB + aoff);
            }
            #pragma unroll
            for (int nf2 = 0; nf2 < 2; ++nf2) {
                int g = lane >> 3;
                int brow = wn * 32 + nf2 * 16 + ((g >> 1) << 3) + (lane & 7);
                int bkc  = ks * 2 + (g & 1);
                uint32_t boff = SWZ128(brow * 128 + bkc * 16);
                ldm_x4(bh[nf2], bhiB + boff);
                ldm_x4(bm[nf2], bmdB + boff);
            }
            #pragma unroll
            for (int mf = 0; mf < 2; ++mf)
                #pragma unroll
                for (int nf2 = 0; nf2 < 2; ++nf2) {
                    float* a0 = acc[mf][nf2 * 2 + 0];
                    float* a1 = acc[mf][nf2 * 2 + 1];
                    mma16816(a0, ah[mf], bh[nf2][0], bh[nf2][1]);   // hh
                    mma16816(a1, ah[mf], bh[nf2][2], bh[nf2][3]);
                    mma16816(a0, ah[mf], bm[nf2][0], bm[nf2][1]);   // hm
                    mma16816(a1, ah[mf], bm[nf2][2], bm[nf2][3]);
                    mma16816(a0, am[mf], bh[nf2][0], bh[nf2][1]);   // mh
                    mma16816(a1, am[mf], bh[nf2][2], bh[nf2][3]);
                }
        }

        // ---- per-chunk epilogue: approx score, fold per-lane top-2 ----
        if (ktile == 7) {
            const int n0 = chunk * BN;
            #pragma unroll
            for (int mf = 0; mf < 2; ++mf) {
                int rA = wm * 32 + mf * 16 + (lane >> 2);
                int rB = rA + 8;
                float x2A = x2s[rA], x2B = x2s[rB];
                #pragma unroll
                for (int nf = 0; nf < 4; ++nf) {
                    int col = wn * 32 + nf * 8 + (lane & 3) * 2;
                    #pragma unroll
                    for (int e = 0; e < 2; ++e) {
                        int idxc = n0 + col + e;
                        float cc = c2s[idxc];
                        float scA = __fsub_rn(__fadd_rn(x2A, cc),
                                              __fmul_rn(2.0f, acc[mf][nf][e]));
                        float scB = __fsub_rn(__fadd_rn(x2B, cc),
                                              __fmul_rn(2.0f, acc[mf][nf][2 + e]));
                        unsigned long long keyA =
                            ((unsigned long long)fmono(scA) << 32) | (unsigned)idxc;
                        unsigned long long keyB =
                            ((unsigned long long)fmono(scB) << 32) | (unsigned)idxc;
                        int sA = mf * 2, sB = mf * 2 + 1;
                        if (keyA < tk1[sA]) { tk2[sA] = tk1[sA]; tk1[sA] = keyA; }
                        else if (keyA < tk2[sA]) tk2[sA] = keyA;
                        if (keyB < tk1[sB]) { tk2[sB] = tk1[sB]; tk1[sB] = keyB; }
                        else if (keyB < tk2[sB]) tk2[sB] = keyB;
                    }
                }
                #pragma unroll
                for (int nf = 0; nf < 4; ++nf)
                    #pragma unroll
                    for (int q = 0; q < 4; ++q) acc[mf][nf][q] = 0.f;
            }
        }
        // no bottom sync: next step's top sync provides the hazard barrier
    }

    // ---- quad merge of per-lane top-2 -> smem per (row, wn) ----
    #pragma unroll
    for (int s = 0; s < 4; ++s) {
        unsigned long long a = tk1[s], b = tk2[s];
        #pragma unroll
        for (int off = 1; off <= 2; off <<= 1) {
            unsigned long long oa = __shfl_xor_sync(0xffffffffu, a, off);
            unsigned long long ob = __shfl_xor_sync(0xffffffffu, b, off);
            unsigned long long n1 = (a < oa) ? a : oa;
            unsigned long long hi = (a < oa) ? oa : a;
            unsigned long long lo2 = (b < ob) ? b : ob;
            b = (hi < lo2) ? hi : lo2;
            a = n1;
        }
        if ((lane & 3) == 0) {
            int row = wm * 32 + (s >> 1) * 16 + (lane >> 2) + (s & 1) * 8;
            topsm[row * 4 + wn * 2 + 0] = a;
            topsm[row * 4 + wn * 2 + 1] = b;
        }
    }
    __syncthreads();

    // ---- fp64 exact rescore of top-2 candidates (warp per row) ----
    const float* cbl = cb + (size_t)layer * KCODES * FDIM;
    for (int m = wid; m < BM; m += 8) {
        if (row0 + m >= nrows) continue;
        unsigned long long k1 = ~0ull, k2 = ~0ull;
        #pragma unroll
        for (int i = 0; i < 4; ++i) {
            unsigned long long v = topsm[m * 4 + i];
            if (v < k1) { k2 = k1; k1 = v; }
            else if (v < k2) k2 = v;
        }
        unsigned c1i = (unsigned)(k1 & 0xFFFFFFFFull);
        unsigned c2i = (unsigned)(k2 & 0xFFFFFFFFull);

        const float* Rr = g_R + (size_t)(row0 + m) * FDIM;
        const float* q1 = cbl + (size_t)c1i * FDIM;
        const float* q2 = cbl + (size_t)c2i * FDIM;
        double d1 = 0.0, d2 = 0.0;
        #pragma unroll
        for (int j = 0; j < 16; ++j) {
            int k = lane + 32 * j;
            double rv = (double)Rr[k];
            d1 += rv * (double)q1[k];
            d2 += rv * (double)q2[k];
        }
        #pragma unroll
        for (int off = 16; off; off >>= 1) {
            d1 += __shfl_xor_sync(0xffffffffu, d1, off);
            d2 += __shfl_xor_sync(0xffffffffu, d2, off);
        }
        if (lane == 0) {
            float x2 = x2s[m];
            float s1 = __fsub_rn(__fadd_rn(x2, c2s[c1i]), __fmul_rn(2.0f, (float)d1));
            float s2 = __fsub_rn(__fadd_rn(x2, c2s[c2i]), __fmul_rn(2.0f, (float)d2));
            unsigned pick;
            if (s1 < s2)      pick = c1i;
            else if (s2 < s1) pick = c2i;
            else              pick = (c1i < c2i) ? c1i : c2i;
            ((unsigned*)(smem + SM_BIDX))[m] = pick;
            size_t o = (size_t)(row0 + m) * NLAYERS + layer;
            if (mode == 0)      ((float*)out_raw)[o] = (float)pick;
            else if (mode == 2) ((long long*)out_raw)[o] = (long long)pick;
        }
    }
    __syncthreads();

    // ---- residual update: warp per row; next-layer splits + x2; recon on last ----
    float* recon = (mode == 1) ? (float*)out_raw
                               : ((float*)out_raw + (size_t)nrows * NLAYERS);
    for (int m = wid; m < BM; m += 8) {
        int row = row0 + m;
        if (row >= nrows) continue;
        unsigned idx = ((unsigned*)(smem + SM_BIDX))[m];
        const float4* cbr = (const float4*)(cb + ((size_t)layer * KCODES + idx) * FDIM);
        float4* Rr = (float4*)(g_R + (size_t)row * FDIM);
        double ss = 0.0;
        #pragma unroll
        for (int j = 0; j < 4; ++j) {
            int q = lane + 32 * j;
            float4 rv = Rr[q], cv = cbr[q];
            rv.x -= cv.x; rv.y -= cv.y; rv.z -= cv.z; rv.w -= cv.w;
            Rr[q] = rv;
            if (layer == NLAYERS - 1) {
                if (mode != 2) {
                    float4 dv = ((const float4*)(data + (size_t)row * FDIM))[q];
                    float4 rc = {dv.x - rv.x, dv.y - rv.y, dv.z - rv.z, dv.w - rv.w};
                    ((float4*)(recon + (size_t)row * FDIM))[q] = rc;
                }
            } else {
                float vv[4] = {rv.x, rv.y, rv.z, rv.w};
                __nv_bfloat16 h[4], md[4];
                #pragma unroll
                for (int c = 0; c < 4; ++c) {
                    split2(vv[c], h[c], md[c]);
                    ss += (double)vv[c] * vv[c];
                }
                size_t e = (size_t)row * FDIM + (size_t)q * 4;
                __nv_bfloat162 t;
                t.x=h[0];  t.y=h[1];  *(__nv_bfloat162*)(g_Rhi+e)   = t;
                t.x=h[2];  t.y=h[3];  *(__nv_bfloat162*)(g_Rhi+e+2) = t;
                t.x=md[0]; t.y=md[1]; *(__nv_bfloat162*)(g_Rmd+e)   = t;
                t.x=md[2]; t.y=md[3]; *(__nv_bfloat162*)(g_Rmd+e+2) = t;
            }
        }
        if (layer != NLAYERS - 1) {
            #pragma unroll
            for (int off = 16; off; off >>= 1) ss += __shfl_xor_sync(0xffffffffu, ss, off);
            if (lane == 0) g_x2[row] = (float)ss;
        }
    }
}

// ---------------- host ----------------
extern "C" void kernel_launch(void* const* d_in, const int* in_sizes, int n_in,
                              void* d_out, int out_size) {
    const float* data = (const float*)d_in[0];
    const float* cb   = (const float*)d_in[1];
    int nrows = in_sizes[0] / FDIM;

    long long n_both  = (long long)nrows * (NLAYERS + FDIM);
    long long n_recon = (long long)nrows * FDIM;
    long long n_codes = (long long)nrows * NLAYERS;
    int mode = 0;
    if ((long long)out_size == n_recon)      mode = 1;
    else if ((long long)out_size == n_codes) mode = 2;
    else if ((long long)out_size == n_both)  mode = 0;

    cudaFuncSetAttribute(layer_kernel, cudaFuncAttributeMaxDynamicSharedMemorySize,
                         SMEM_TOTAL);

    cbprep_kernel<<<(NLAYERS * KCODES * FDIM / 4 + 255) / 256, 256>>>(cb);
    c2_kernel<<<(NLAYERS * KCODES + 7) / 8, 256>>>(cb);
    init_kernel<<<(nrows + 7) / 8, 256>>>(data, nrows);

    int grid = (nrows + BM - 1) / BM;
    for (int l = 0; l < NLAYERS; ++l)
        layer_kernel<<<grid, NTHREADS, SMEM_TOTAL>>>(cb, data, d_out, nrows, l, mode);
}